// round 10
// baseline (speedup 1.0000x reference)
#include <cuda_runtime.h>
#include <cuda_fp16.h>
#include <cstdint>

#define CIN    128
#define OUTC   128
#define T_IN   32768
#define P_OUT  32769
#define NTILES 2056          // 257 p-tiles * 8 batches
#define GRID   304           // 2 CTAs per SM

#define WP 132               // u64 pitch, W pair rows (conflict-free LDS.64)

// smem: W image + bias only (68.1 KB -> easily 2 CTAs/SM)
#define SM_W    0                        // u64 [64][WP] = 67584
#define SM_BIAS 67584
#define SM_TOT  68096

typedef unsigned long long u64;

// W image: [pr][o] u64 = { lo32: f16x2 pair(kr=r), hi32: f16x2 pair(kr=r+4) }
// pair(kr) = f16x2 { lo: W[o][2kr], hi: W[o][2kr+1] },  r = 8*(pr>>2) + (pr&3)
// For k-step klg: pr = 4*klg + t  ->  lo = pair(8klg+t) [k 2t,2t+1], hi = pair(8klg+t+4) [k 2t+8,2t+9]
__device__ __align__(16) u64 g_W64[64 * WP];

__device__ __forceinline__ uint32_t cvt2h(float hi, float lo) {
    uint32_t r;
    asm("cvt.rn.f16x2.f32 %0, %1, %2;" : "=r"(r) : "f"(hi), "f"(lo));
    return r;
}
__device__ __forceinline__ void mma16816h(float* d, const uint32_t* a, uint32_t b0, uint32_t b1) {
    asm volatile(
        "mma.sync.aligned.m16n8k16.row.col.f32.f16.f16.f32 "
        "{%0,%1,%2,%3}, {%4,%5,%6,%7}, {%8,%9}, {%0,%1,%2,%3};"
        : "+f"(d[0]), "+f"(d[1]), "+f"(d[2]), "+f"(d[3])
        : "r"(a[0]), "r"(a[1]), "r"(a[2]), "r"(a[3]), "r"(b0), "r"(b1));
}

__global__ void prep_W(const float* __restrict__ W) {
    int idx = blockIdx.x * blockDim.x + threadIdx.x;   // 8192
    int pr = idx >> 7, o = idx & 127;
    int r = ((pr >> 2) << 3) | (pr & 3);
    uint32_t pa = cvt2h(W[o * 256 + 2 * r + 1],       W[o * 256 + 2 * r]);
    uint32_t pb = cvt2h(W[o * 256 + 2 * (r + 4) + 1], W[o * 256 + 2 * (r + 4)]);
    g_W64[pr * WP + o] = ((u64)pb << 32) | pa;
}

// Load one k-step of B data: 16 floats = per nf (4): x[c0][p], x[c0][p+2], x[c1][p], x[c1][p+2]
// pa points at x[c0][p0 + pgrp*32 + g]; c1 = c0 + 4 channels.
__device__ __forceinline__ void loadB_fast(const float* __restrict__ pa, float* pf) {
    const float* pb = pa + 4 * T_IN;
    #pragma unroll
    for (int nf = 0; nf < 4; ++nf) {
        pf[4*nf + 0] = pa[8*nf];
        pf[4*nf + 1] = pa[8*nf + 2];
        pf[4*nf + 2] = pb[8*nf];
        pf[4*nf + 3] = pb[8*nf + 2];
    }
}
__device__ __forceinline__ void loadB_slow(const float* __restrict__ pa, int rem, float* pf) {
    const float* pb = pa + 4 * T_IN;
    #pragma unroll
    for (int nf = 0; nf < 4; ++nf) {
        pf[4*nf + 0] = (8*nf     < rem) ? pa[8*nf]     : 0.0f;
        pf[4*nf + 1] = (8*nf + 2 < rem) ? pa[8*nf + 2] : 0.0f;
        pf[4*nf + 2] = (8*nf     < rem) ? pb[8*nf]     : 0.0f;
        pf[4*nf + 3] = (8*nf + 2 < rem) ? pb[8*nf + 2] : 0.0f;
    }
}

__global__ __launch_bounds__(256, 2)
void dconv10(const float* __restrict__ x,
             const float* __restrict__ bias,
             float* __restrict__ out)
{
    extern __shared__ char smem[];
    u64*   sW    = reinterpret_cast<u64*>(smem + SM_W);
    float* sBias = reinterpret_cast<float*>(smem + SM_BIAS);

    const int tid = threadIdx.x;
    const int lane = tid & 31;
    const int t = lane & 3;
    const int g = lane >> 2;
    const int warp = tid >> 5;
    const int ob   = (warp >> 2) * 64;   // M: output base (2 groups)
    const int pgrp = (warp & 3);         // N: position group (4 x 32 pos)
    const int bx = blockIdx.x;
    const int nt = (NTILES - 1 - bx) / GRID + 1;

    // one-time: W image + bias
    {
        const uint4* src = reinterpret_cast<const uint4*>(g_W64);
        uint4* dst = reinterpret_cast<uint4*>(sW);
        #pragma unroll 4
        for (int i = tid; i < 4224; i += 256) dst[i] = src[i];
    }
    if (tid < 128) sBias[tid] = bias[tid];
    __syncthreads();

    for (int tt = 0; tt < nt; ++tt) {
        const int tile = bx + tt * GRID;
        const int b = tile & 7;
        const long p0 = (long)(tile >> 3) * 128;
        const int basepos = (int)p0 + pgrp * 32 + g;     // this lane's base position
        const bool fast = (p0 + 130 <= T_IN);
        const int rem = T_IN - basepos;                  // elems valid from basepos

        float acc[4][4][4];
        #pragma unroll
        for (int mf = 0; mf < 4; ++mf)
            #pragma unroll
            for (int nf = 0; nf < 4; ++nf)
                #pragma unroll
                for (int i = 0; i < 4; ++i) acc[mf][nf][i] = 0.0f;

        // lane base pointer: channel t, position basepos
        const float* pa = x + (size_t)b * CIN * T_IN + (size_t)t * T_IN + basepos;

        float pf[16];
        if (fast) loadB_fast(pa, pf); else loadB_slow(pa, rem, pf);

        #pragma unroll 4
        for (int klg = 0; klg < 16; ++klg) {
            // build B frags from prefetched floats
            uint32_t bf[8];
            #pragma unroll
            for (int nf = 0; nf < 4; ++nf) {
                bf[2*nf]     = cvt2h(pf[4*nf + 1], pf[4*nf + 0]);  // b0: kr = 8klg+t
                bf[2*nf + 1] = cvt2h(pf[4*nf + 3], pf[4*nf + 2]);  // b1: kr = 8klg+t+4
            }
            // prefetch next k-step (8 channels ahead)
            if (klg < 15) {
                pa += 8 * T_IN;
                if (fast) loadB_fast(pa, pf); else loadB_slow(pa, rem, pf);
            }
            // W A-frags + MMA
            const u64* wr = sW + (size_t)(4 * klg + t) * WP;
            #pragma unroll
            for (int mf = 0; mf < 4; ++mf) {
                const int o = ob + 16 * mf + g;
                u64 wA = wr[o];       // rows o:   a0 (lo), a2 (hi)
                u64 wB = wr[o + 8];   // rows o+8: a1 (lo), a3 (hi)
                uint32_t a[4] = { (uint32_t)wA, (uint32_t)wB,
                                  (uint32_t)(wA >> 32), (uint32_t)(wB >> 32) };
                #pragma unroll
                for (int nf = 0; nf < 4; ++nf)
                    mma16816h(acc[mf][nf], a, bf[2*nf], bf[2*nf + 1]);
            }
        }

        // epilogue: rows = outputs, cols = positions
        #pragma unroll
        for (int mf = 0; mf < 4; ++mf) {
            const int o = ob + 16 * mf + g;
            const float b0 = sBias[o], b1 = sBias[o + 8];
            #pragma unroll
            for (int nf = 0; nf < 4; ++nf) {
                long p = p0 + pgrp * 32 + 8 * nf + 2 * t;
                float* r0 = out + ((size_t)b * OUTC + o) * P_OUT + p;
                float* r1 = r0 + (size_t)8 * P_OUT;
                if (p < P_OUT) {
                    r0[0] = acc[mf][nf][0] + b0;
                    r1[0] = acc[mf][nf][2] + b1;
                }
                if (p + 1 < P_OUT) {
                    r0[1] = acc[mf][nf][1] + b0;
                    r1[1] = acc[mf][nf][3] + b1;
                }
            }
        }
    }
}

extern "C" void kernel_launch(void* const* d_in, const int* in_sizes, int n_in,
                              void* d_out, int out_size)
{
    const float* x  = (const float*)d_in[0];   // (8, 128, 32768)
    const float* W  = (const float*)d_in[1];   // (128, 128, 2)
    const float* bs = (const float*)d_in[2];   // (128,)
    float* out = (float*)d_out;                // (8, 128, 32769)

    cudaFuncSetAttribute(dconv10, cudaFuncAttributeMaxDynamicSharedMemorySize, SM_TOT);

    prep_W<<<32, 256>>>(W);
    dconv10<<<GRID, 256, SM_TOT>>>(x, bs, out);
}

// round 11
// speedup vs baseline: 1.2787x; 1.2787x over previous
#include <cuda_runtime.h>
#include <cuda_fp16.h>
#include <cstdint>

#define CIN    128
#define OUTC   128
#define T_IN   32768
#define P_OUT  32769
#define NTILES 2056          // 257 p-tiles * 8 batches
#define GRID   304           // 2 CTAs per SM

#define WP 132               // u64 pitch, W pair rows (conflict-free LDS.64)
#define XP 136               // f32 pitch, x chunk rows (bank = 8t+g, conflict-free)
#define CHUNK_ROWS 16        // channels per chunk
#define CHUNK_U32  (CHUNK_ROWS * XP)   // 2176 u32 = 8704 B
#define NCHT 8               // chunks per tile (128 channels)

// smem byte offsets (total 102912 B -> 2 CTAs/SM)
#define SM_W    0                          // u64 [64][WP] = 67584
#define SM_X    67584                      // f32, 4 stages x 8704 = 34816
#define SM_BIAS (SM_X + 4 * CHUNK_U32 * 4) // 102400
#define SM_TOT  (SM_BIAS + 512)            // 102912

typedef unsigned long long u64;

// W image: [pr][o] u64 = { lo32: f16x2 pair(kr=r), hi32: f16x2 pair(kr=r+4) }
// pair(kr) = f16x2 { lo: W[o][2kr], hi: W[o][2kr+1] },  r = 8*(pr>>2) + (pr&3)
__device__ __align__(16) u64 g_W64[64 * WP];

__device__ __forceinline__ uint32_t smem_u32(const void* p) {
    uint32_t a;
    asm("{ .reg .u64 t; cvta.to.shared.u64 t, %1; cvt.u32.u64 %0, t; }" : "=r"(a) : "l"(p));
    return a;
}
__device__ __forceinline__ uint32_t cvt2h(float hi, float lo) {
    uint32_t r;
    asm("cvt.rn.f16x2.f32 %0, %1, %2;" : "=r"(r) : "f"(hi), "f"(lo));
    return r;
}
__device__ __forceinline__ void mma16816h(float* d, const uint32_t* a, uint32_t b0, uint32_t b1) {
    asm volatile(
        "mma.sync.aligned.m16n8k16.row.col.f32.f16.f16.f32 "
        "{%0,%1,%2,%3}, {%4,%5,%6,%7}, {%8,%9}, {%0,%1,%2,%3};"
        : "+f"(d[0]), "+f"(d[1]), "+f"(d[2]), "+f"(d[3])
        : "r"(a[0]), "r"(a[1]), "r"(a[2]), "r"(a[3]), "r"(b0), "r"(b1));
}

__global__ void prep_W(const float* __restrict__ W) {
    int idx = blockIdx.x * blockDim.x + threadIdx.x;   // 8192
    int pr = idx >> 7, o = idx & 127;
    int r = ((pr >> 2) << 3) | (pr & 3);
    uint32_t pa = cvt2h(W[o * 256 + 2 * r + 1],       W[o * 256 + 2 * r]);
    uint32_t pb = cvt2h(W[o * 256 + 2 * (r + 4) + 1], W[o * 256 + 2 * (r + 4)]);
    g_W64[pr * WP + o] = ((u64)pb << 32) | pa;
}

// Issue one 16-channel chunk via cp.async: 16 rows x 34 x 16B = 544 ops, zero-filled at edges.
__device__ __forceinline__ void issue_chunk(const float* __restrict__ x,
                                            int tid, int j, int bx, uint32_t xb) {
    const int tile = bx + (j >> 3) * GRID;
    const int b = tile & 7;
    const long p0 = (long)(tile >> 3) * 128;
    const int cb = (j & 7) * CHUNK_ROWS;
    const uint32_t slot = (uint32_t)(j & 3) * (CHUNK_U32 * 4);
    #pragma unroll
    for (int k = 0; k < 3; ++k) {
        int op = tid + k * 256;
        if (op < 16 * 34) {
            int row = op / 34, unit = op - row * 34;
            long p = p0 + unit * 4;
            int valid = (int)((long)T_IN - p);
            int sbytes = valid >= 4 ? 16 : (valid > 0 ? valid * 4 : 0);
            const float* src = x + ((size_t)b * CIN + (size_t)(cb + row)) * T_IN + p;
            if (sbytes == 0) src = x;     // keep address in-bounds; full zero-fill
            uint32_t dst = xb + slot + (uint32_t)(row * XP + unit * 4) * 4u;
            asm volatile("cp.async.ca.shared.global [%0], [%1], 16, %2;"
                         :: "r"(dst), "l"(src), "r"(sbytes) : "memory");
        }
    }
}

__global__ __launch_bounds__(256, 2)
void dconv11(const float* __restrict__ x,
             const float* __restrict__ bias,
             float* __restrict__ out)
{
    extern __shared__ char smem[];
    u64*         sW    = reinterpret_cast<u64*>(smem + SM_W);
    const float* sX    = reinterpret_cast<const float*>(smem + SM_X);
    float*       sBias = reinterpret_cast<float*>(smem + SM_BIAS);
    const uint32_t xb  = smem_u32(smem) + SM_X;

    const int tid = threadIdx.x;
    const int lane = tid & 31;
    const int t = lane & 3;
    const int g = lane >> 2;
    const int warp = tid >> 5;
    const int ob   = (warp >> 2) * 64;   // M: output base
    const int pgrp = (warp & 3);         // N: 32-position group
    const int bx = blockIdx.x;
    const int nt = (NTILES - 1 - bx) / GRID + 1;
    const int nctot = nt * NCHT;

    // one-time: W image + bias
    {
        const uint4* src = reinterpret_cast<const uint4*>(g_W64);
        uint4* dst = reinterpret_cast<uint4*>(sW);
        #pragma unroll 4
        for (int i = tid; i < 4224; i += 256) dst[i] = src[i];
    }
    if (tid < 128) sBias[tid] = bias[tid];
    __syncthreads();

    float acc[4][4][4];
    #pragma unroll
    for (int mf = 0; mf < 4; ++mf)
        #pragma unroll
        for (int nf = 0; nf < 4; ++nf)
            #pragma unroll
            for (int i = 0; i < 4; ++i) acc[mf][nf][i] = 0.0f;

    // prologue: 3 chunk-groups in flight
    #pragma unroll
    for (int j0 = 0; j0 < 3; ++j0) {
        if (j0 < nctot) issue_chunk(x, tid, j0, bx, xb);
        asm volatile("cp.async.commit_group;" ::: "memory");
    }

    for (int j = 0; j < nctot; ++j) {
        asm volatile("cp.async.wait_group 2;" ::: "memory");
        __syncthreads();                       // chunk j visible; slot (j-1)&3 fully consumed
        if (j + 3 < nctot) issue_chunk(x, tid, j + 3, bx, xb);
        asm volatile("cp.async.commit_group;" ::: "memory");

        // ---- MMA chunk j: 2 k-steps ----
        const float* Xc = sX + (size_t)(j & 3) * CHUNK_U32;
        #pragma unroll
        for (int kk = 0; kk < 2; ++kk) {
            const int klg = (j & 7) * 2 + kk;
            // B frags from raw f32 smem (conflict-free: bank = 8t+g)
            const float* xr = Xc + (size_t)(8 * kk + t) * XP + pgrp * 32 + g;
            uint32_t bf[8];
            #pragma unroll
            for (int nf = 0; nf < 4; ++nf) {
                float v0 = xr[8 * nf],          v2 = xr[8 * nf + 2];
                float w0 = xr[4 * XP + 8 * nf], w2 = xr[4 * XP + 8 * nf + 2];
                bf[2 * nf]     = cvt2h(v2, v0);
                bf[2 * nf + 1] = cvt2h(w2, w0);
            }
            const u64* wr = sW + (size_t)(4 * klg + t) * WP;
            #pragma unroll
            for (int mf = 0; mf < 4; ++mf) {
                const int o = ob + 16 * mf + g;
                u64 wA = wr[o], wB = wr[o + 8];
                uint32_t a[4] = { (uint32_t)wA, (uint32_t)wB,
                                  (uint32_t)(wA >> 32), (uint32_t)(wB >> 32) };
                #pragma unroll
                for (int nf = 0; nf < 4; ++nf)
                    mma16816h(acc[mf][nf], a, bf[2 * nf], bf[2 * nf + 1]);
            }
        }

        // ---- tile boundary: epilogue ----
        if ((j & 7) == 7) {
            const int tile = bx + (j >> 3) * GRID;
            const int b = tile & 7;
            const long p0 = (long)(tile >> 3) * 128;
            #pragma unroll
            for (int mf = 0; mf < 4; ++mf) {
                const int o = ob + 16 * mf + g;
                const float b0 = sBias[o], b1 = sBias[o + 8];
                #pragma unroll
                for (int nf = 0; nf < 4; ++nf) {
                    long p = p0 + pgrp * 32 + 8 * nf + 2 * t;
                    float* r0 = out + ((size_t)b * OUTC + o) * P_OUT + p;
                    float* r1 = r0 + (size_t)8 * P_OUT;
                    if (p < P_OUT) {
                        r0[0] = acc[mf][nf][0] + b0;
                        r1[0] = acc[mf][nf][2] + b1;
                    }
                    if (p + 1 < P_OUT) {
                        r0[1] = acc[mf][nf][1] + b0;
                        r1[1] = acc[mf][nf][3] + b1;
                    }
                    #pragma unroll
                    for (int k = 0; k < 4; ++k) acc[mf][nf][k] = 0.0f;
                }
            }
        }
    }
}

extern "C" void kernel_launch(void* const* d_in, const int* in_sizes, int n_in,
                              void* d_out, int out_size)
{
    const float* x  = (const float*)d_in[0];   // (8, 128, 32768)
    const float* W  = (const float*)d_in[1];   // (128, 128, 2)
    const float* bs = (const float*)d_in[2];   // (128,)
    float* out = (float*)d_out;                // (8, 128, 32769)

    cudaFuncSetAttribute(dconv11, cudaFuncAttributeMaxDynamicSharedMemorySize, SM_TOT);

    prep_W<<<32, 256>>>(W);
    dconv11<<<GRID, 256, SM_TOT>>>(x, bs, out);
}

// round 12
// speedup vs baseline: 1.3472x; 1.0536x over previous
#include <cuda_runtime.h>
#include <cuda_fp16.h>
#include <cstdint>

#define CIN    128
#define OUTC   128
#define T_IN   32768
#define P_OUT  32769
#define NTILE2 4104          // 513 p-tiles(64 pos) * 8 batches
#define NSTR   608           // 304 CTAs * 2 half-streams
#define GRID   304

#define WP 132               // u64 pitch, W pair rows (conflict-free LDS.64)
#define XP 72                // f32 pitch, x rows (bank = 8t+g, conflict-free)
#define NSTAGE 5
#define CHUNK_F32 (16 * XP)          // 1152 f32 = 4608 B per chunk
#define XHALF_B   (NSTAGE * CHUNK_F32 * 4)   // 23040 B per half

// smem byte offsets (114176 B per CTA -> 2 CTAs/SM)
#define SM_W    0                    // u64 [64][WP] = 67584
#define SM_X    67584                // 2 halves x 5 stages x 4608
#define SM_BIAS (SM_X + 2 * XHALF_B) // 113664
#define SM_TOT  (SM_BIAS + 512)      // 114176

typedef unsigned long long u64;

// W image: [pr][o] u64 = { lo32: f16x2 pair(kr=r), hi32: f16x2 pair(kr=r+4) }
__device__ __align__(16) u64 g_W64[64 * WP];

__device__ __forceinline__ uint32_t smem_u32(const void* p) {
    uint32_t a;
    asm("{ .reg .u64 t; cvta.to.shared.u64 t, %1; cvt.u32.u64 %0, t; }" : "=r"(a) : "l"(p));
    return a;
}
__device__ __forceinline__ uint32_t cvt2h(float hi, float lo) {
    uint32_t r;
    asm("cvt.rn.f16x2.f32 %0, %1, %2;" : "=r"(r) : "f"(hi), "f"(lo));
    return r;
}
__device__ __forceinline__ void mma16816h(float* d, const uint32_t* a, uint32_t b0, uint32_t b1) {
    asm volatile(
        "mma.sync.aligned.m16n8k16.row.col.f32.f16.f16.f32 "
        "{%0,%1,%2,%3}, {%4,%5,%6,%7}, {%8,%9}, {%0,%1,%2,%3};"
        : "+f"(d[0]), "+f"(d[1]), "+f"(d[2]), "+f"(d[3])
        : "r"(a[0]), "r"(a[1]), "r"(a[2]), "r"(a[3]), "r"(b0), "r"(b1));
}
__device__ __forceinline__ void nbar(int id) {
    asm volatile("bar.sync %0, 128;" :: "r"(id) : "memory");
}

__global__ void prep_W(const float* __restrict__ W) {
    int idx = blockIdx.x * blockDim.x + threadIdx.x;   // 8192
    int pr = idx >> 7, o = idx & 127;
    int r = ((pr >> 2) << 3) | (pr & 3);
    uint32_t pa = cvt2h(W[o * 256 + 2 * r + 1],       W[o * 256 + 2 * r]);
    uint32_t pb = cvt2h(W[o * 256 + 2 * (r + 4) + 1], W[o * 256 + 2 * (r + 4)]);
    g_W64[pr * WP + o] = ((u64)pb << 32) | pa;
}

// issue one chunk (16 channels x 68 floats) for stream sid via cp.async
__device__ __forceinline__ void issue_chunk(const float* __restrict__ x,
                                            int tidh, int j, int sid, uint32_t xbh) {
    const int tile = sid + (j >> 3) * NSTR;
    const int b = tile & 7;
    const long p0 = (long)(tile >> 3) * 64;
    const int cb = (j & 7) * 16;
    const uint32_t slot = (uint32_t)(j % NSTAGE) * (CHUNK_F32 * 4);
    #pragma unroll
    for (int k = 0; k < 3; ++k) {
        int op = tidh + k * 128;
        if (op < 16 * 17) {
            int row = op / 17, u = op - row * 17;
            long p = p0 + u * 4;
            int valid = (int)((long)T_IN - p);
            int sbytes = valid >= 4 ? 16 : (valid > 0 ? valid * 4 : 0);
            const float* src = x + ((size_t)b * CIN + (size_t)(cb + row)) * T_IN + p;
            if (sbytes == 0) src = x;
            uint32_t dst = xbh + slot + (uint32_t)(row * XP + u * 4) * 4u;
            asm volatile("cp.async.ca.shared.global [%0], [%1], 16, %2;"
                         :: "r"(dst), "l"(src), "r"(sbytes) : "memory");
        }
    }
}

__global__ __launch_bounds__(256, 2)
void dconv12(const float* __restrict__ x,
             const float* __restrict__ bias,
             float* __restrict__ out)
{
    extern __shared__ char smem[];
    u64*         sW    = reinterpret_cast<u64*>(smem + SM_W);
    float*       sBias = reinterpret_cast<float*>(smem + SM_BIAS);

    const int tid = threadIdx.x;
    const int lane = tid & 31;
    const int t = lane & 3;
    const int g = lane >> 2;
    const int wid = tid >> 5;
    const int h    = wid >> 2;          // half-stream 0/1
    const int widh = wid & 3;
    const int ob   = (widh >> 1) * 64;  // M: output base
    const int pgrp = widh & 1;          // N: 32-position group
    const int tidh = tid & 127;

    const uint32_t xbh = smem_u32(smem) + SM_X + (uint32_t)h * XHALF_B;
    const float* sXh = reinterpret_cast<const float*>(smem + SM_X) + (size_t)h * (NSTAGE * CHUNK_F32);

    const int sid = blockIdx.x * 2 + h;
    const int nt  = (NTILE2 - 1 - sid) / NSTR + 1;
    const int nc  = nt * 8;

    // one-time: W image + bias (whole CTA)
    {
        const uint4* src = reinterpret_cast<const uint4*>(g_W64);
        uint4* dst = reinterpret_cast<uint4*>(sW);
        #pragma unroll 4
        for (int i = tid; i < 4224; i += 256) dst[i] = src[i];
    }
    if (tid < 128) sBias[tid] = bias[tid];
    __syncthreads();

    float acc[4][4][4];
    #pragma unroll
    for (int mf = 0; mf < 4; ++mf)
        #pragma unroll
        for (int nf = 0; nf < 4; ++nf)
            #pragma unroll
            for (int i = 0; i < 4; ++i) acc[mf][nf][i] = 0.0f;

    // prologue: 4 chunks in flight
    #pragma unroll
    for (int j0 = 0; j0 < 4; ++j0) {
        if (j0 < nc) issue_chunk(x, tidh, j0, sid, xbh);
        asm volatile("cp.async.commit_group;" ::: "memory");
    }

    for (int j = 0; j < nc; ++j) {
        asm volatile("cp.async.wait_group 3;" ::: "memory");
        nbar(1 + h);                       // chunk j visible; slot (j-1)%5 consumed by all
        if (j + 4 < nc) issue_chunk(x, tidh, j + 4, sid, xbh);
        asm volatile("cp.async.commit_group;" ::: "memory");

        // ---- consume chunk j: 2 k-steps ----
        const float* Xc = sXh + (size_t)(j % NSTAGE) * CHUNK_F32;
        #pragma unroll
        for (int kk = 0; kk < 2; ++kk) {
            const int klg = (j & 7) * 2 + kk;
            const float* xr = Xc + (size_t)(8 * kk + t) * XP + pgrp * 32 + g;
            uint32_t bf[8];
            #pragma unroll
            for (int nf = 0; nf < 4; ++nf) {
                float v0 = xr[8 * nf],          v2 = xr[8 * nf + 2];
                float w0 = xr[4 * XP + 8 * nf], w2 = xr[4 * XP + 8 * nf + 2];
                bf[2 * nf]     = cvt2h(v2, v0);
                bf[2 * nf + 1] = cvt2h(w2, w0);
            }
            const u64* wr = sW + (size_t)(4 * klg + t) * WP;
            #pragma unroll
            for (int mf = 0; mf < 4; ++mf) {
                const int o = ob + 16 * mf + g;
                u64 wA = wr[o], wB = wr[o + 8];
                uint32_t a[4] = { (uint32_t)wA, (uint32_t)wB,
                                  (uint32_t)(wA >> 32), (uint32_t)(wB >> 32) };
                #pragma unroll
                for (int nf = 0; nf < 4; ++nf)
                    mma16816h(acc[mf][nf], a, bf[2 * nf], bf[2 * nf + 1]);
            }
        }

        // ---- tile boundary: epilogue ----
        if ((j & 7) == 7) {
            const int tile = sid + (j >> 3) * NSTR;
            const int b = tile & 7;
            const long p0 = (long)(tile >> 3) * 64;
            #pragma unroll
            for (int mf = 0; mf < 4; ++mf) {
                const int o = ob + 16 * mf + g;
                const float b0 = sBias[o], b1 = sBias[o + 8];
                #pragma unroll
                for (int nf = 0; nf < 4; ++nf) {
                    long p = p0 + pgrp * 32 + 8 * nf + 2 * t;
                    float* r0 = out + ((size_t)b * OUTC + o) * P_OUT + p;
                    float* r1 = r0 + (size_t)8 * P_OUT;
                    if (p < P_OUT) {
                        r0[0] = acc[mf][nf][0] + b0;
                        r1[0] = acc[mf][nf][2] + b1;
                    }
                    if (p + 1 < P_OUT) {
                        r0[1] = acc[mf][nf][1] + b0;
                        r1[1] = acc[mf][nf][3] + b1;
                    }
                    #pragma unroll
                    for (int k = 0; k < 4; ++k) acc[mf][nf][k] = 0.0f;
                }
            }
        }
    }
}

extern "C" void kernel_launch(void* const* d_in, const int* in_sizes, int n_in,
                              void* d_out, int out_size)
{
    const float* x  = (const float*)d_in[0];   // (8, 128, 32768)
    const float* W  = (const float*)d_in[1];   // (128, 128, 2)
    const float* bs = (const float*)d_in[2];   // (128,)
    float* out = (float*)d_out;                // (8, 128, 32769)

    cudaFuncSetAttribute(dconv12, cudaFuncAttributeMaxDynamicSharedMemorySize, SM_TOT);

    prep_W<<<32, 256>>>(W);
    dconv12<<<GRID, 256, SM_TOT>>>(x, bs, out);
}

// round 13
// speedup vs baseline: 1.3484x; 1.0009x over previous
#include <cuda_runtime.h>
#include <cuda_fp16.h>
#include <cstdint>

#define CIN    128
#define OUTC   128
#define T_IN   32768
#define P_OUT  32769
#define NTILE2 4104          // 513 p-tiles(64 pos) * 8 batches
#define NSTR   608           // 304 CTAs * 2 half-streams
#define GRID   304

#define WP 132               // u64 pitch, W pair rows (conflict-free LDS.64)
#define XP 72                // f32 pitch, x rows (bank = 8t+g, conflict-free; 288B, 16B-aligned)
#define NSTAGE 5
#define LOOKAHEAD 3
#define CHUNK_B   (16 * XP * 4)      // 4608 B per chunk (16 channels x 72 f32)
#define XHALF_B   (NSTAGE * CHUNK_B) // 23040 B per half

// smem byte offsets (114336 B per CTA -> 2 CTAs/SM)
#define SM_W    0                      // u64 [64][WP] = 67584
#define SM_X    67584                  // 2 halves x 5 stages x 4608 = 46080
#define SM_BIAS 113664                 // 512
#define SM_MBAR 114176                 // 2 halves x (5 full + 5 empty) x 8B = 160
#define SM_TOT  114336

typedef unsigned long long u64;

// W image: [pr][o] u64 = { lo32: f16x2 pair(kr=r), hi32: f16x2 pair(kr=r+4) }
__device__ __align__(16) u64 g_W64[64 * WP];

__device__ __forceinline__ uint32_t smem_u32(const void* p) {
    uint32_t a;
    asm("{ .reg .u64 t; cvta.to.shared.u64 t, %1; cvt.u32.u64 %0, t; }" : "=r"(a) : "l"(p));
    return a;
}
__device__ __forceinline__ uint32_t cvt2h(float hi, float lo) {
    uint32_t r;
    asm("cvt.rn.f16x2.f32 %0, %1, %2;" : "=r"(r) : "f"(hi), "f"(lo));
    return r;
}
__device__ __forceinline__ void mma16816h(float* d, const uint32_t* a, uint32_t b0, uint32_t b1) {
    asm volatile(
        "mma.sync.aligned.m16n8k16.row.col.f32.f16.f16.f32 "
        "{%0,%1,%2,%3}, {%4,%5,%6,%7}, {%8,%9}, {%0,%1,%2,%3};"
        : "+f"(d[0]), "+f"(d[1]), "+f"(d[2]), "+f"(d[3])
        : "r"(a[0]), "r"(a[1]), "r"(a[2]), "r"(a[3]), "r"(b0), "r"(b1));
}
__device__ __forceinline__ void mbar_init(uint32_t m, uint32_t cnt) {
    asm volatile("mbarrier.init.shared.b64 [%0], %1;" :: "r"(m), "r"(cnt) : "memory");
}
__device__ __forceinline__ void mbar_expect_tx(uint32_t m, uint32_t bytes) {
    asm volatile("mbarrier.arrive.expect_tx.shared.b64 _, [%0], %1;" :: "r"(m), "r"(bytes) : "memory");
}
__device__ __forceinline__ void mbar_arrive(uint32_t m) {
    asm volatile("mbarrier.arrive.shared.b64 _, [%0];" :: "r"(m) : "memory");
}
__device__ __forceinline__ void mbar_wait(uint32_t m, uint32_t parity) {
    asm volatile(
        "{\n\t.reg .pred P1;\n\t"
        "WAIT_%=:\n\t"
        "mbarrier.try_wait.parity.acquire.cta.shared::cta.b64 P1, [%0], %1, 0x989680;\n\t"
        "@P1 bra.uni DONE_%=;\n\t"
        "bra.uni WAIT_%=;\n\t"
        "DONE_%=:\n\t}" :: "r"(m), "r"(parity) : "memory");
}
__device__ __forceinline__ void bulk_g2s(uint32_t dst, const void* src, uint32_t bytes, uint32_t mbar) {
    asm volatile(
        "cp.async.bulk.shared::cta.global.mbarrier::complete_tx::bytes [%0], [%1], %2, [%3];"
        :: "r"(dst), "l"(src), "r"(bytes), "r"(mbar) : "memory");
}

__global__ void prep_W(const float* __restrict__ W) {
    int idx = blockIdx.x * blockDim.x + threadIdx.x;   // 8192
    int pr = idx >> 7, o = idx & 127;
    int r = ((pr >> 2) << 3) | (pr & 3);
    uint32_t pa = cvt2h(W[o * 256 + 2 * r + 1],       W[o * 256 + 2 * r]);
    uint32_t pb = cvt2h(W[o * 256 + 2 * (r + 4) + 1], W[o * 256 + 2 * (r + 4)]);
    g_W64[pr * WP + o] = ((u64)pb << 32) | pa;
}

// Producer (warp 0 of each half): stage chunk jj via cp.async.bulk.
__device__ __forceinline__ void produce(const float* __restrict__ x, char* smem,
                                        int jj, int sid, int lane,
                                        uint32_t xbh, uint32_t mbh, int half) {
    const int s = jj % NSTAGE;
    const uint32_t full  = mbh + (uint32_t)s * 8;
    const uint32_t empty = mbh + 40 + (uint32_t)s * 8;
    if (jj >= NSTAGE) mbar_wait(empty, (uint32_t)(((jj - NSTAGE) / NSTAGE) & 1));

    const int tile = sid + (jj >> 3) * NSTR;
    const int b = tile & 7;
    const long p0 = (long)(tile >> 3) * 64;
    const int cb = (jj & 7) * 16;
    const uint32_t slot = xbh + (uint32_t)s * CHUNK_B;

    long vf64 = (long)T_IN - p0;
    int vbytes = (vf64 >= 68) ? 272 : (vf64 > 0 ? (int)vf64 * 4 : 0);  // multiple of 16 by construction

    if (vbytes < 272) {
        // zero-fill tails (rare edge tiles)
        char* slotp = smem + SM_X + (size_t)half * XHALF_B + (size_t)s * CHUNK_B;
        if (vbytes == 0) {
            for (int i = lane; i < CHUNK_B / 16; i += 32)
                *reinterpret_cast<uint4*>(slotp + i * 16) = make_uint4(0, 0, 0, 0);
        } else if (lane < 16) {
            for (int off = vbytes; off < 272; off += 16)
                *reinterpret_cast<uint4*>(slotp + lane * (XP * 4) + off) = make_uint4(0, 0, 0, 0);
        }
        __syncwarp();
    }
    if (lane == 0) {
        if (vbytes > 0) mbar_expect_tx(full, (uint32_t)(16 * vbytes));
        else            mbar_arrive(full);
    }
    __syncwarp();
    if (lane < 16 && vbytes > 0) {
        const float* src = x + ((size_t)b * CIN + (size_t)(cb + lane)) * T_IN + p0;
        bulk_g2s(slot + (uint32_t)lane * (XP * 4), src, (uint32_t)vbytes, full);
    }
}

__global__ __launch_bounds__(256, 2)
void dconv13(const float* __restrict__ x,
             const float* __restrict__ bias,
             float* __restrict__ out)
{
    extern __shared__ char smem[];
    u64*   sW    = reinterpret_cast<u64*>(smem + SM_W);
    float* sBias = reinterpret_cast<float*>(smem + SM_BIAS);

    const int tid = threadIdx.x;
    const int lane = tid & 31;
    const int t = lane & 3;
    const int g = lane >> 2;
    const int wid = tid >> 5;
    const int h    = wid >> 2;          // half-stream 0/1
    const int widh = wid & 3;
    const int ob   = (widh >> 1) * 64;  // M: output base
    const int pgrp = widh & 1;          // N: 32-position group

    const uint32_t sb  = smem_u32(smem);
    const uint32_t xbh = sb + SM_X + (uint32_t)h * XHALF_B;
    const uint32_t mbh = sb + SM_MBAR + (uint32_t)h * 80;
    const float* sXh = reinterpret_cast<const float*>(smem + SM_X) + (size_t)h * (XHALF_B / 4);

    const int sid = blockIdx.x * 2 + h;
    const int nt  = (NTILE2 - 1 - sid) / NSTR + 1;
    const int nc  = nt * 8;

    // one-time: W image + bias + mbarrier init
    {
        const uint4* src = reinterpret_cast<const uint4*>(g_W64);
        uint4* dst = reinterpret_cast<uint4*>(sW);
        #pragma unroll 4
        for (int i = tid; i < 4224; i += 256) dst[i] = src[i];
    }
    if (tid < 128) sBias[tid] = bias[tid];
    if (tid == 0) {
        #pragma unroll
        for (int hh = 0; hh < 2; ++hh)
            #pragma unroll
            for (int s = 0; s < NSTAGE; ++s) {
                mbar_init(sb + SM_MBAR + hh * 80 + s * 8, 1);        // full: 1 arrive + tx
                mbar_init(sb + SM_MBAR + hh * 80 + 40 + s * 8, 4);   // empty: 4 warps
            }
    }
    __syncthreads();

    float acc[4][4][4];
    #pragma unroll
    for (int mf = 0; mf < 4; ++mf)
        #pragma unroll
        for (int nf = 0; nf < 4; ++nf)
            #pragma unroll
            for (int i = 0; i < 4; ++i) acc[mf][nf][i] = 0.0f;

    // prologue: producer stages first LOOKAHEAD chunks
    if (widh == 0) {
        #pragma unroll
        for (int j0 = 0; j0 < LOOKAHEAD; ++j0)
            if (j0 < nc) produce(x, smem, j0, sid, lane, xbh, mbh, h);
    }

    for (int j = 0; j < nc; ++j) {
        if (widh == 0 && j + LOOKAHEAD < nc)
            produce(x, smem, j + LOOKAHEAD, sid, lane, xbh, mbh, h);

        const int s = j % NSTAGE;
        mbar_wait(mbh + (uint32_t)s * 8, (uint32_t)((j / NSTAGE) & 1));

        // ---- consume chunk j: 2 k-steps ----
        const float* Xc = sXh + (size_t)s * (CHUNK_B / 4);
        #pragma unroll
        for (int kk = 0; kk < 2; ++kk) {
            const int klg = (j & 7) * 2 + kk;
            const float* xr = Xc + (size_t)(8 * kk + t) * XP + pgrp * 32 + g;
            uint32_t bf[8];
            #pragma unroll
            for (int nf = 0; nf < 4; ++nf) {
                float v0 = xr[8 * nf],          v2 = xr[8 * nf + 2];
                float w0 = xr[4 * XP + 8 * nf], w2 = xr[4 * XP + 8 * nf + 2];
                bf[2 * nf]     = cvt2h(v2, v0);
                bf[2 * nf + 1] = cvt2h(w2, w0);
            }
            const u64* wr = sW + (size_t)(4 * klg + t) * WP;
            #pragma unroll
            for (int mf = 0; mf < 4; ++mf) {
                const int o = ob + 16 * mf + g;
                u64 wA = wr[o], wB = wr[o + 8];
                uint32_t a[4] = { (uint32_t)wA, (uint32_t)wB,
                                  (uint32_t)(wA >> 32), (uint32_t)(wB >> 32) };
                #pragma unroll
                for (int nf = 0; nf < 4; ++nf)
                    mma16816h(acc[mf][nf], a, bf[2 * nf], bf[2 * nf + 1]);
            }
        }
        if (lane == 0) mbar_arrive(mbh + 40 + (uint32_t)s * 8);   // empty arrive (per warp)

        // ---- tile boundary: epilogue ----
        if ((j & 7) == 7) {
            const int tile = sid + (j >> 3) * NSTR;
            const int b = tile & 7;
            const long p0 = (long)(tile >> 3) * 64;
            #pragma unroll
            for (int mf = 0; mf < 4; ++mf) {
                const int o = ob + 16 * mf + g;
                const float b0 = sBias[o], b1 = sBias[o + 8];
                #pragma unroll
                for (int nf = 0; nf < 4; ++nf) {
                    long p = p0 + pgrp * 32 + 8 * nf + 2 * t;
                    float* r0 = out + ((size_t)b * OUTC + o) * P_OUT + p;
                    float* r1 = r0 + (size_t)8 * P_OUT;
                    if (p < P_OUT) {
                        r0[0] = acc[mf][nf][0] + b0;
                        r1[0] = acc[mf][nf][2] + b1;
                    }
                    if (p + 1 < P_OUT) {
                        r0[1] = acc[mf][nf][1] + b0;
                        r1[1] = acc[mf][nf][3] + b1;
                    }
                    #pragma unroll
                    for (int k = 0; k < 4; ++k) acc[mf][nf][k] = 0.0f;
                }
            }
        }
    }
}

extern "C" void kernel_launch(void* const* d_in, const int* in_sizes, int n_in,
                              void* d_out, int out_size)
{
    const float* x  = (const float*)d_in[0];   // (8, 128, 32768)
    const float* W  = (const float*)d_in[1];   // (128, 128, 2)
    const float* bs = (const float*)d_in[2];   // (128,)
    float* out = (float*)d_out;                // (8, 128, 32769)

    cudaFuncSetAttribute(dconv13, cudaFuncAttributeMaxDynamicSharedMemorySize, SM_TOT);

    prep_W<<<32, 256>>>(W);
    dconv13<<<GRID, 256, SM_TOT>>>(x, bs, out);
}